// round 2
// baseline (speedup 1.0000x reference)
#include <cuda_runtime.h>
#include <cstdint>

// DeNuCLoss: top-4 matching loss.
// bs=8, nq=16384, ng=1024, N_CLS=1 (logits 2 classes), TOP_K=4
// COST_POINT=0.1, COST_CLASS=1.0, REG_COEF=5.0, CLS_COEF=1.0
//
// 6 graph-capturable launches:
//   k_pre     : per-query (x,y,-p0,-p1) pack, nll pair, match=0, mask dtype detect,
//               per-block sum of nll1 (cls base)
//   k_compact : warp-ballot per-batch compaction of valid gts (deterministic order)
//   k_top     : HOT. thread = one gt, scans a 1024-query split, private top-4.
//   k_merge   : combine QSPLIT partials per gt, exact tie-break; reg-loss partials,
//               match flags
//   k_cls     : matched-label correction sum
//   k_final   : reduce partials, emit 2 outputs

#define BS 8
#define NQ 16384
#define NG 1024
#define QSPLIT 16
#define QS (NQ / QSPLIT)          // 1024 queries per split
#define NGRP 4                    // gt groups of 256 per batch
#define NBLK_PRE 512
#define NBLK_CLS 512
#define NBLK_MRG 32               // (NG/256) * BS

__device__ float4        g_qdata[BS * NQ];          // x, y, -p0, -p1
__device__ float2        g_nll[BS * NQ];            // (lse-l0, lse-l1)
__device__ unsigned char g_match[BS * NQ];
__device__ int           g_valid_list[BS][NG];
__device__ int           g_valid_cnt[BS];
__device__ int           g_lab_nz[BS];
__device__ int           g_mask_kind;               // 0=int32,1=bytes,2=float32
__device__ float4        g_part_v[BS * NG * QSPLIT];
__device__ int4          g_part_i[BS * NG * QSPLIT];
__device__ float         g_cls1_part[NBLK_PRE];
__device__ float         g_cls2_part[NBLK_CLS];
__device__ float         g_reg_part[NBLK_MRG];

__device__ __forceinline__ float fast_sqrtf(float x) {
    float r;
    asm("sqrt.approx.f32 %0, %1;" : "=f"(r) : "f"(x));
    return r;
}

// jax top_k order: smaller cost wins; exact tie -> smaller query index wins.
__device__ __forceinline__ bool better(float va, int ia, float vb, int ib) {
    return (va < vb) || (va == vb && ia < ib);
}

__device__ __forceinline__ float block_reduce_256(float v) {
    __shared__ float ws[8];
#pragma unroll
    for (int off = 16; off; off >>= 1) v += __shfl_xor_sync(0xffffffffu, v, off);
    if ((threadIdx.x & 31) == 0) ws[threadIdx.x >> 5] = v;
    __syncthreads();
    float t = 0.0f;
    if (threadIdx.x < 8) t = ws[threadIdx.x];
    if (threadIdx.x < 8) {
#pragma unroll
        for (int off = 4; off; off >>= 1) t += __shfl_xor_sync(0xffu, t, off);
    }
    return t;   // valid in thread 0
}

// ---------------------------------------------------------------------------
__global__ __launch_bounds__(256) void k_pre(const float* __restrict__ pc,
                                             const float* __restrict__ pl,
                                             const unsigned char* __restrict__ mask_raw) {
    int i = blockIdx.x * 256 + threadIdx.x;   // covers BS*NQ exactly with 512 blocks
    float x  = pc[2 * i], y = pc[2 * i + 1];
    float l0 = pl[2 * i], l1 = pl[2 * i + 1];
    float m  = fmaxf(l0, l1);
    float e0 = expf(l0 - m), e1 = expf(l1 - m);
    float sum = e0 + e1;
    float inv = 1.0f / sum;
    float lse = m + logf(sum);
    g_qdata[i] = make_float4(x, y, -e0 * inv, -e1 * inv);
    g_nll[i]   = make_float2(lse - l0, lse - l1);
    g_match[i] = 0;

    float part = block_reduce_256(lse - l1);      // base: all labels assumed N_CLS
    if (threadIdx.x == 0) g_cls1_part[blockIdx.x] = part;

    if (blockIdx.x == 0 && threadIdx.x == 0) {
        // Detect gt_masks storage from raw bytes of first 64 elements.
        bool any_mis = false, b1nz = false, any3f = false;
        for (int t = 0; t < 256; t++) {
            unsigned char v = mask_raw[t];
            if ((t & 3) != 0 && v) {
                any_mis = true;
                if ((t & 3) == 1) b1nz = true;
                if (v == 0x3F) any3f = true;
            }
        }
        int kind;
        if (!any_mis)            kind = 0;   // int32 {0,1}
        else if (!b1nz && any3f) kind = 2;   // float32 {0.0,1.0}
        else                     kind = 1;   // bool / int8 bytes
        g_mask_kind = kind;
    }
}

// ---------------------------------------------------------------------------
// One warp per batch; ballot-based stable compaction (list ascending in g).
__global__ __launch_bounds__(256) void k_compact(const void* __restrict__ mask,
                                                 const int* __restrict__ gtl) {
    int b    = threadIdx.x >> 5;
    int lane = threadIdx.x & 31;
    int kind = g_mask_kind;
    int cnt = 0, labnz = 0;
    for (int j = 0; j < NG; j += 32) {
        int g = j + lane;
        int i = b * NG + g;
        bool m;
        if (kind == 0)      m = ((const int*)mask)[i] != 0;
        else if (kind == 1) m = ((const unsigned char*)mask)[i] != 0;
        else                m = ((const float*)mask)[i] != 0.0f;
        unsigned bal = __ballot_sync(0xffffffffu, m);
        if (m) {
            int pos = cnt + __popc(bal & ((1u << lane) - 1u));
            g_valid_list[b][pos] = g;
            if (gtl[i] != 0) labnz = 1;
        }
        cnt += __popc(bal);
    }
    unsigned lb = __ballot_sync(0xffffffffu, labnz);
    if (lane == 0) { g_valid_cnt[b] = cnt; g_lab_nz[b] = (lb != 0); }
}

// ---------------------------------------------------------------------------
// HOT kernel. Block = (gt-group of 256, query-split of 1024, batch).
// Thread = one gt. Private sorted top-4, strict-< insert (earlier qi kept on tie).
// ---------------------------------------------------------------------------
#define INSERT4(cst, qi)                                              \
    {                                                                  \
        if ((cst) < v1) {                                              \
            v3 = v2; i3 = i2; v2 = v1; i2 = i1;                        \
            if ((cst) < v0) { v1 = v0; i1 = i0; v0 = (cst); i0 = (qi); } \
            else            { v1 = (cst); i1 = (qi); }                 \
        } else {                                                       \
            if ((cst) < v2) { v3 = v2; i3 = i2; v2 = (cst); i2 = (qi); } \
            else            { v3 = (cst); i3 = (qi); }                 \
        }                                                              \
    }

__global__ __launch_bounds__(256) void k_top(const float* __restrict__ gtc,
                                             const int* __restrict__ gtl) {
    __shared__ float4 sq[QS];                 // 16 KB
    const int b     = blockIdx.y;
    const int cnt   = g_valid_cnt[b];
    const int ggrp  = blockIdx.x & (NGRP - 1);
    const int split = blockIdx.x >> 2;        // log2(NGRP)
    if (ggrp * 256 >= cnt) return;            // block-uniform early exit

    const int qb = split * QS;
    for (int t = threadIdx.x; t < QS; t += 256)
        sq[t] = g_qdata[b * NQ + qb + t];
    __syncthreads();

    const int slot  = ggrp * 256 + threadIdx.x;
    const int slotc = min(slot, cnt - 1);
    const int gi    = g_valid_list[b][slotc];
    const float gx  = gtc[(b * NG + gi) * 2];
    const float gy  = gtc[(b * NG + gi) * 2 + 1];
    const bool  l0  = (gtl[b * NG + gi] == 0);

    const float PINF = __int_as_float(0x7f800000);
    float v0 = PINF, v1 = PINF, v2 = PINF, v3 = PINF;
    int   i0 = 0x7fffffff, i1 = 0x7fffffff, i2 = 0x7fffffff, i3 = 0x7fffffff;

    if (!g_lab_nz[b]) {
        // All valid labels are 0 -> class term is q.z, no select.
#pragma unroll 8
        for (int j = 0; j < QS; j++) {
            float4 q = sq[j];
            float dx = q.x - gx, dy = q.y - gy;
            float ss = fmaf(dx, dx, dy * dy);
            float d  = fast_sqrtf(ss);
            float cst = fmaf(0.1f, d, q.z);
            if (cst < v3) { int qi = qb + j; INSERT4(cst, qi); }
        }
    } else {
#pragma unroll 8
        for (int j = 0; j < QS; j++) {
            float4 q = sq[j];
            float dx = q.x - gx, dy = q.y - gy;
            float ss = fmaf(dx, dx, dy * dy);
            float d  = fast_sqrtf(ss);
            float cst = fmaf(0.1f, d, l0 ? q.z : q.w);
            if (cst < v3) { int qi = qb + j; INSERT4(cst, qi); }
        }
    }

    if (slot < cnt) {
        int o = (b * NG + slot) * QSPLIT + split;
        g_part_v[o] = make_float4(v0, v1, v2, v3);
        g_part_i[o] = make_int4(i0, i1, i2, i3);
    }
}

// ---------------------------------------------------------------------------
// Combine per-split partials -> final top-4 per gt; reg-loss partial + flags.
// ---------------------------------------------------------------------------
__global__ __launch_bounds__(256) void k_merge(const float* __restrict__ gtc) {
    const int b    = blockIdx.y;
    const int slot = blockIdx.x * 256 + threadIdx.x;
    const int cnt  = g_valid_cnt[b];
    float s = 0.0f;
    if (slot < cnt) {
        const float PINF = __int_as_float(0x7f800000);
        float v0 = PINF, v1 = PINF, v2 = PINF, v3 = PINF;
        int   i0 = 0x7fffffff, i1 = 0x7fffffff, i2 = 0x7fffffff, i3 = 0x7fffffff;
        int base = (b * NG + slot) * QSPLIT;
#pragma unroll
        for (int sp = 0; sp < QSPLIT; sp++) {
            float4 pv = g_part_v[base + sp];
            int4   pi = g_part_i[base + sp];
            float cv[4] = {pv.x, pv.y, pv.z, pv.w};
            int   ci[4] = {pi.x, pi.y, pi.z, pi.w};
#pragma unroll
            for (int k = 0; k < 4; k++) {
                float nv = cv[k]; int ni = ci[k];
                if (better(nv, ni, v3, i3)) {
                    if (better(nv, ni, v1, i1)) {
                        v3 = v2; i3 = i2; v2 = v1; i2 = i1;
                        if (better(nv, ni, v0, i0)) { v1 = v0; i1 = i0; v0 = nv; i0 = ni; }
                        else                        { v1 = nv; i1 = ni; }
                    } else {
                        if (better(nv, ni, v2, i2)) { v3 = v2; i3 = i2; v2 = nv; i2 = ni; }
                        else                        { v3 = nv; i3 = ni; }
                    }
                }
            }
        }
        const int gi = g_valid_list[b][slot];
        const float gx = gtc[(b * NG + gi) * 2];
        const float gy = gtc[(b * NG + gi) * 2 + 1];
        int idxs[4] = {i0, i1, i2, i3};
#pragma unroll
        for (int k = 0; k < 4; k++) {
            float4 q = g_qdata[b * NQ + idxs[k]];
            float dx = q.x - gx, dy = q.y - gy;
            s += dx * dx + dy * dy;
            g_match[b * NQ + idxs[k]] = 1;
        }
    }
    float part = block_reduce_256(s);
    if (threadIdx.x == 0) g_reg_part[blockIdx.y * (NG / 256) + blockIdx.x] = part;
}

// ---------------------------------------------------------------------------
// Matched-label correction: sum over matched queries of (nll0 - nll1).
// ---------------------------------------------------------------------------
__global__ __launch_bounds__(256) void k_cls() {
    int i = blockIdx.x * 256 + threadIdx.x;
    float c = 0.0f;
    if (g_match[i]) {
        float2 n = g_nll[i];
        c = n.x - n.y;
    }
    float part = block_reduce_256(c);
    if (threadIdx.x == 0) g_cls2_part[blockIdx.x] = part;
}

// ---------------------------------------------------------------------------
__global__ __launch_bounds__(256) void k_final(float* __restrict__ out) {
    float a = 0.0f, r = 0.0f;
    for (int i = threadIdx.x; i < NBLK_PRE; i += 256) a += g_cls1_part[i] + g_cls2_part[i];
    if (threadIdx.x < NBLK_MRG) r = g_reg_part[threadIdx.x];

    __shared__ float sa[8], sr[8];
#pragma unroll
    for (int off = 16; off; off >>= 1) {
        a += __shfl_xor_sync(0xffffffffu, a, off);
        r += __shfl_xor_sync(0xffffffffu, r, off);
    }
    if ((threadIdx.x & 31) == 0) { sa[threadIdx.x >> 5] = a; sr[threadIdx.x >> 5] = r; }
    __syncthreads();
    if (threadIdx.x == 0) {
        float A = 0.0f, R = 0.0f;
#pragma unroll
        for (int w = 0; w < 8; w++) { A += sa[w]; R += sr[w]; }
        int n = 0;
#pragma unroll
        for (int b = 0; b < BS; b++) n += g_valid_cnt[b];
        float denom = 8.0f * (float)(n > 0 ? n : 1);   // n_valid*TOP_K*2 = 8n
        out[0] = 5.0f * R / denom;
        out[1] = A / (float)(BS * NQ);
    }
}

extern "C" void kernel_launch(void* const* d_in, const int* in_sizes, int n_in,
                              void* d_out, int out_size) {
    const float* pc   = (const float*)d_in[0];   // pred_coords (8,16384,2)
    const float* pl   = (const float*)d_in[1];   // pred_logits (8,16384,2)
    const float* gtc  = (const float*)d_in[2];   // gt_coords   (8,1024,2)
    const int*   gtl  = (const int*)d_in[3];     // gt_labels   (8,1024)
    const void*  gmsk = d_in[4];                 // gt_masks    (8,1024), dtype-detected

    k_pre<<<NBLK_PRE, 256>>>(pc, pl, (const unsigned char*)gmsk);
    k_compact<<<1, 256>>>(gmsk, gtl);
    k_top<<<dim3(NGRP * QSPLIT, BS), 256>>>(gtc, gtl);
    k_merge<<<dim3(NG / 256, BS), 256>>>(gtc);
    k_cls<<<NBLK_CLS, 256>>>();
    k_final<<<1, 256>>>((float*)d_out);
}

// round 6
// speedup vs baseline: 1.4502x; 1.4502x over previous
#include <cuda_runtime.h>
#include <cstdint>

// DeNuCLoss: top-4 matching loss via sorted-scan with provable early exit.
// bs=8, nq=16384, ng=1024, N_CLS=1 (2-class logits), TOP_K=4
// cost = 0.1*dist(q,g) - p_label(q); since cost >= -p(q), scanning queries in
// descending-p order lets each gt stop once suffix-min(-p) > its 4th-best cost.
//
// 6 launches: k_compact, k_pre, k_scan, k_scatter, k_top (w/ fused suffix-min),
// k_final.

#define BS 8
#define NQ 16384
#define NG 1024
#define NBINS 256
#define NBLK 512                   // (BS*NQ)/256
#define NCHUNK 512                 // NQ/32 chunks per batch

__device__ float4        g_sq[BS * NQ];        // sorted: x, y, -p0, idx(bits)
__device__ float         g_sp1[BS * NQ];       // sorted: -p1 (only if labels mixed)
__device__ int           g_match[BS * NQ];
__device__ unsigned char g_bin[BS * NQ];
__device__ unsigned int  g_blockhist[NBLK * NBINS];
__device__ unsigned int  g_blockoff[NBLK * NBINS];
__device__ unsigned int  g_base[BS * NBINS];
__device__ unsigned int  g_chunkU[BS * NCHUNK];
__device__ int           g_valid_list[BS][NG];
__device__ int           g_valid_cnt[BS];
__device__ int           g_lab_nz[BS];
__device__ int           g_mask_kind;
__device__ float         g_cls1_part[NBLK];
__device__ float         g_cls2;               // matched-label correction (atomic)
__device__ float         g_reg_part[16 * BS];

__device__ __forceinline__ float fast_sqrtf(float x) {
    float r;
    asm("sqrt.approx.f32 %0, %1;" : "=f"(r) : "f"(x));
    return r;
}

// jax top_k total order: smaller cost wins; exact tie -> smaller query index.
__device__ __forceinline__ bool better(float va, int ia, float vb, int ib) {
    return (va < vb) || (va == vb && ia < ib);
}

__device__ __forceinline__ float block_reduce_256(float v) {
    __shared__ float ws[8];
#pragma unroll
    for (int off = 16; off; off >>= 1) v += __shfl_xor_sync(0xffffffffu, v, off);
    if ((threadIdx.x & 31) == 0) ws[threadIdx.x >> 5] = v;
    __syncthreads();
    float t = 0.0f;
    if (threadIdx.x < 8) {
        t = ws[threadIdx.x];
#pragma unroll
        for (int off = 4; off; off >>= 1) t += __shfl_xor_sync(0xffu, t, off);
    }
    return t;   // valid in thread 0
}

// ---------------------------------------------------------------------------
// k_compact: mask dtype detect + per-batch valid-gt list + label-nonzero flag
// + zero scalar/partial accumulators (graph-replay safety).
// ---------------------------------------------------------------------------
__global__ __launch_bounds__(256) void k_compact(const void* __restrict__ mask,
                                                 const int* __restrict__ gtl) {
    if (threadIdx.x == 0) {
        const unsigned char* mb = (const unsigned char*)mask;
        bool any_mis = false, b1nz = false, any3f = false;
        for (int t = 0; t < 256; t++) {
            unsigned char v = mb[t];
            if ((t & 3) != 0 && v) {
                any_mis = true;
                if ((t & 3) == 1) b1nz = true;
                if (v == 0x3F) any3f = true;
            }
        }
        int kind;
        if (!any_mis)            kind = 0;   // int32 {0,1}
        else if (!b1nz && any3f) kind = 2;   // float32 {0.0,1.0}
        else                     kind = 1;   // bool / int8 bytes
        g_mask_kind = kind;
        g_cls2 = 0.0f;
    }
    if (threadIdx.x < 16 * BS) g_reg_part[threadIdx.x] = 0.0f;
    __syncthreads();
    int b    = threadIdx.x >> 5;
    int lane = threadIdx.x & 31;
    int kind = g_mask_kind;
    int cnt = 0, labnz = 0;
    for (int j = 0; j < NG; j += 32) {
        int g = j + lane;
        int i = b * NG + g;
        bool m;
        if (kind == 0)      m = ((const int*)mask)[i] != 0;
        else if (kind == 1) m = ((const unsigned char*)mask)[i] != 0;
        else                m = ((const float*)mask)[i] != 0.0f;
        unsigned bal = __ballot_sync(0xffffffffu, m);
        if (m) {
            int pos = cnt + __popc(bal & ((1u << lane) - 1u));
            g_valid_list[b][pos] = g;
            if (gtl[i] != 0) labnz = 1;
        }
        cnt += __popc(bal);
    }
    unsigned lb = __ballot_sync(0xffffffffu, labnz);
    if (lane == 0) { g_valid_cnt[b] = cnt; g_lab_nz[b] = (lb != 0); }
}

// ---------------------------------------------------------------------------
// k_pre: softmax, bin assignment, per-block histogram, cls base partial,
// zero match flags + chunk-min scratch.
// ---------------------------------------------------------------------------
__global__ __launch_bounds__(256) void k_pre(const float* __restrict__ pl) {
    __shared__ unsigned int sh[NBINS];
    sh[threadIdx.x] = 0;
    __syncthreads();

    int i = blockIdx.x * 256 + threadIdx.x;
    int b = i >> 14;
    float l0 = pl[2 * i], l1 = pl[2 * i + 1];
    float m  = fmaxf(l0, l1);
    float e0 = __expf(l0 - m), e1 = __expf(l1 - m);
    float sum = e0 + e1;
    float inv = 1.0f / sum;
    float p0 = e0 * inv, p1 = e1 * inv;
    float lse = m + __logf(sum);
    float key = g_lab_nz[b] ? fmaxf(p0, p1) : p0;
    int bin = min(NBINS - 1, (int)(key * 256.0f));
    g_bin[i] = (unsigned char)bin;
    g_match[i] = 0;
    atomicAdd(&sh[bin], 1u);
    if (blockIdx.x < 16) g_chunkU[blockIdx.x * 256 + threadIdx.x] = 0;
    __syncthreads();
    g_blockhist[blockIdx.x * NBINS + threadIdx.x] = sh[threadIdx.x];

    float part = block_reduce_256(lse - l1);      // base: all labels assumed N_CLS
    if (threadIdx.x == 0) g_cls1_part[blockIdx.x] = part;
}

// ---------------------------------------------------------------------------
// k_scan: per-batch per-bin exclusive scan over blocks + descending-bin bases.
// ---------------------------------------------------------------------------
__global__ __launch_bounds__(256) void k_scan() {
    int b = blockIdx.x, t = threadIdx.x;
    unsigned acc = 0;
    for (int j = 0; j < 64; j++) {
        int idx = (b * 64 + j) * NBINS + t;
        unsigned v = g_blockhist[idx];
        g_blockoff[idx] = acc;
        acc += v;
    }
    __shared__ unsigned tot[NBINS];
    __shared__ unsigned base[NBINS];
    tot[t] = acc;
    __syncthreads();
    if (t == 0) {
        unsigned a = 0;
        for (int r = NBINS - 1; r >= 0; r--) { base[r] = a; a += tot[r]; }
    }
    __syncthreads();
    g_base[b * NBINS + t] = base[t];
}

// ---------------------------------------------------------------------------
// k_scatter: place each query at its sorted position; record chunk min key.
// (atomicMax on raw bits == float min, since every key is strictly negative.)
// ---------------------------------------------------------------------------
__global__ __launch_bounds__(256) void k_scatter(const float* __restrict__ pc,
                                                 const float* __restrict__ pl) {
    __shared__ unsigned int scnt[NBINS];
    scnt[threadIdx.x] = 0;
    __syncthreads();

    int i = blockIdx.x * 256 + threadIdx.x;
    int b = i >> 14;
    int qi = i & (NQ - 1);
    float x  = pc[2 * i], y = pc[2 * i + 1];
    float l0 = pl[2 * i], l1 = pl[2 * i + 1];
    float m  = fmaxf(l0, l1);
    float e0 = __expf(l0 - m), e1 = __expf(l1 - m);
    float inv = 1.0f / (e0 + e1);
    float p0 = e0 * inv, p1 = e1 * inv;
    int bin = g_bin[i];
    int lab = g_lab_nz[b];

    unsigned rank = atomicAdd(&scnt[bin], 1u);
    unsigned pos = g_base[b * NBINS + bin] + g_blockoff[blockIdx.x * NBINS + bin] + rank;

    g_sq[b * NQ + pos] = make_float4(x, y, -p0, __int_as_float(qi));
    float zkey = lab ? -fmaxf(p0, p1) : -p0;
    atomicMax(&g_chunkU[b * NCHUNK + (pos >> 5)], __float_as_uint(zkey));
    if (lab) g_sp1[b * NQ + pos] = -p1;
}

// ---------------------------------------------------------------------------
// k_top: thread = one valid gt; scan sorted queries, early-exit via suffix-min
// (computed in-block from g_chunkU). Epilogue: reg-loss partial + match flags
// with atomicExch dedup + cls correction (l1-l0 per first-matched query).
// ---------------------------------------------------------------------------
#define INS(cst, qi, ps)                                                      \
    if (better(cst, qi, v3, i3)) {                                            \
        if (better(cst, qi, v1, i1)) {                                        \
            v3 = v2; i3 = i2; s3 = s2; v2 = v1; i2 = i1; s2 = s1;             \
            if (better(cst, qi, v0, i0)) {                                    \
                v1 = v0; i1 = i0; s1 = s0; v0 = cst; i0 = qi; s0 = ps;        \
            } else { v1 = cst; i1 = qi; s1 = ps; }                            \
        } else if (better(cst, qi, v2, i2)) {                                 \
            v3 = v2; i3 = i2; s3 = s2; v2 = cst; i2 = qi; s2 = ps;            \
        } else { v3 = cst; i3 = qi; s3 = ps; }                                \
    }

__global__ __launch_bounds__(64) void k_top(const float* __restrict__ gtc,
                                            const int* __restrict__ gtl,
                                            const float* __restrict__ pl) {
    __shared__ float ssuf[NCHUNK];
    __shared__ float w2[2], w2c[2];
    const int b   = blockIdx.y;
    const int cnt = g_valid_cnt[b];
    if ((int)blockIdx.x * 64 >= cnt) return;   // partials pre-zeroed in k_compact

    // Load chunk mins and suffix-min scan them in smem (race-free Hillis-Steele).
    const float PINF = __int_as_float(0x7f800000);
#pragma unroll
    for (int r = 0; r < NCHUNK / 64; r++)
        ssuf[threadIdx.x + r * 64] =
            __uint_as_float(g_chunkU[b * NCHUNK + threadIdx.x + r * 64]);
    __syncthreads();
    for (int off = 1; off < NCHUNK; off <<= 1) {
        float vals[NCHUNK / 64];
#pragma unroll
        for (int r = 0; r < NCHUNK / 64; r++) {
            int t = threadIdx.x + r * 64;
            vals[r] = (t + off < NCHUNK) ? ssuf[t + off] : PINF;
        }
        __syncthreads();
#pragma unroll
        for (int r = 0; r < NCHUNK / 64; r++) {
            int t = threadIdx.x + r * 64;
            ssuf[t] = fminf(ssuf[t], vals[r]);
        }
        __syncthreads();
    }

    const int slot  = blockIdx.x * 64 + threadIdx.x;
    const bool act  = slot < cnt;
    const int slotc = act ? slot : 0;
    const int gi    = g_valid_list[b][slotc];
    const float gx  = gtc[(b * NG + gi) * 2];
    const float gy  = gtc[(b * NG + gi) * 2 + 1];
    const bool lab0 = (gtl[b * NG + gi] == 0);

    const float NINF = __int_as_float(0xff800000);
    float v0 = PINF, v1 = PINF, v2 = PINF, v3 = act ? PINF : NINF;
    int i0 = 0x7fffffff, i1 = 0x7fffffff, i2 = 0x7fffffff, i3 = 0x7fffffff;
    int s0 = 0, s1 = 0, s2 = 0, s3 = 0;

    const float4* __restrict__ qb = g_sq + b * NQ;

    if (!g_lab_nz[b]) {
        for (int c = 0; c < NCHUNK; c++) {
            if (ssuf[c] > v3) break;       // nothing remaining can beat v3
            int cb = c * 32;
#pragma unroll 4
            for (int jj = 0; jj < 32; jj++) {
                float4 q = qb[cb + jj];
                float dx = q.x - gx, dy = q.y - gy;
                float cst = fmaf(0.1f, fast_sqrtf(fmaf(dx, dx, dy * dy)), q.z);
                if (cst <= v3) {
                    int qi = __float_as_int(q.w);
                    int ps = cb + jj;
                    INS(cst, qi, ps);
                }
            }
        }
    } else {
        const float* __restrict__ z1 = g_sp1 + b * NQ;
        for (int c = 0; c < NCHUNK; c++) {
            if (ssuf[c] > v3) break;
            int cb = c * 32;
            for (int jj = 0; jj < 32; jj++) {
                float4 q = qb[cb + jj];
                float zc = lab0 ? q.z : z1[cb + jj];
                float dx = q.x - gx, dy = q.y - gy;
                float cst = fmaf(0.1f, fast_sqrtf(fmaf(dx, dx, dy * dy)), zc);
                if (cst <= v3) {
                    int qi = __float_as_int(q.w);
                    int ps = cb + jj;
                    INS(cst, qi, ps);
                }
            }
        }
    }

    float s = 0.0f, corr = 0.0f;
    if (act) {
        int ss4[4] = {s0, s1, s2, s3};
        int ii4[4] = {i0, i1, i2, i3};
#pragma unroll
        for (int k = 0; k < 4; k++) {
            float4 q = qb[ss4[k]];
            float dx = q.x - gx, dy = q.y - gy;
            s += dx * dx + dy * dy;
            int gidx = b * NQ + ii4[k];
            int old = atomicExch(&g_match[gidx], 1);
            if (!old)   // first matcher pays the cls correction: nll0-nll1 = l1-l0
                corr += pl[2 * gidx + 1] - pl[2 * gidx];
        }
    }
#pragma unroll
    for (int off = 16; off; off >>= 1) {
        s    += __shfl_xor_sync(0xffffffffu, s, off);
        corr += __shfl_xor_sync(0xffffffffu, corr, off);
    }
    if ((threadIdx.x & 31) == 0) {
        w2[threadIdx.x >> 5]  = s;
        w2c[threadIdx.x >> 5] = corr;
    }
    __syncthreads();
    if (threadIdx.x == 0) {
        g_reg_part[blockIdx.y * 16 + blockIdx.x] = w2[0] + w2[1];
        float c2 = w2c[0] + w2c[1];
        if (c2 != 0.0f) atomicAdd(&g_cls2, c2);
    }
}

// ---------------------------------------------------------------------------
__global__ __launch_bounds__(256) void k_final(float* __restrict__ out) {
    float a = 0.0f, r = 0.0f;
    for (int i = threadIdx.x; i < NBLK; i += 256) a += g_cls1_part[i];
    if (threadIdx.x < 16 * BS) r = g_reg_part[threadIdx.x];

    __shared__ float sa[8], sr[8];
#pragma unroll
    for (int off = 16; off; off >>= 1) {
        a += __shfl_xor_sync(0xffffffffu, a, off);
        r += __shfl_xor_sync(0xffffffffu, r, off);
    }
    if ((threadIdx.x & 31) == 0) { sa[threadIdx.x >> 5] = a; sr[threadIdx.x >> 5] = r; }
    __syncthreads();
    if (threadIdx.x == 0) {
        float A = 0.0f, R = 0.0f;
#pragma unroll
        for (int w = 0; w < 8; w++) { A += sa[w]; R += sr[w]; }
        A += g_cls2;
        int n = 0;
#pragma unroll
        for (int b = 0; b < BS; b++) n += g_valid_cnt[b];
        float denom = 8.0f * (float)(n > 0 ? n : 1);   // n_valid*TOP_K*2
        out[0] = 5.0f * R / denom;
        out[1] = A / (float)(BS * NQ);
    }
}

extern "C" void kernel_launch(void* const* d_in, const int* in_sizes, int n_in,
                              void* d_out, int out_size) {
    const float* pc   = (const float*)d_in[0];   // pred_coords (8,16384,2)
    const float* pl   = (const float*)d_in[1];   // pred_logits (8,16384,2)
    const float* gtc  = (const float*)d_in[2];   // gt_coords   (8,1024,2)
    const int*   gtl  = (const int*)d_in[3];     // gt_labels   (8,1024)
    const void*  gmsk = d_in[4];                 // gt_masks    (8,1024), dtype-detected

    k_compact<<<1, 256>>>(gmsk, gtl);
    k_pre<<<NBLK, 256>>>(pl);
    k_scan<<<BS, 256>>>();
    k_scatter<<<NBLK, 256>>>(pc, pl);
    k_top<<<dim3(16, BS), 64>>>(gtc, gtl, pl);
    k_final<<<1, 256>>>((float*)d_out);
}

// round 11
// speedup vs baseline: 1.9026x; 1.3120x over previous
#include <cuda_runtime.h>
#include <cstdint>

// DeNuCLoss: top-4 matching loss, single persistent kernel with software grid
// barriers. bs=8, nq=16384, ng=1024, N_CLS=1, TOP_K=4.
// cost = 0.1*dist(q,g) - p_label(q) >= -key, key = p0 if all labels in the
// batch are 0 (mask-independent check), else max(p0,p1). Queries bucket-sorted
// by descending key; each gt (split 4 ways across lanes) scans until the
// suffix-min of -key over remaining chunks exceeds its 4th-best cost.
//
// Phases (grid barriers between): A softmax+hist+compact | B suffix-sum bases
// | C scatter+chunk keys | D split top-4 + losses | E output + cleanup.

#define BS 8
#define NQ 16384
#define NG 1024
#define NBINS 256
#define NCHUNK 512                 // NQ/32
#define NBLOCKS 128
#define NTHREADS 256
#define GSZ (NBLOCKS * NTHREADS)

__device__ float4   g_sq[BS * NQ];        // sorted: x, y, -p0, idx(bits)
__device__ float    g_sp1[BS * NQ];       // sorted: -p1 (only if labels mixed)
__device__ int      g_match[BS * NQ];     // zero-init; reset in-kernel each run
__device__ unsigned g_hist[BS * NBINS];   // zero-init; reset at end each run
__device__ unsigned g_cursor[BS * NBINS];
__device__ unsigned g_chunkU[BS * NCHUNK];// zero-init; reset at end each run
__device__ int      g_valid_list[BS][NG];
__device__ int      g_valid_cnt[BS];
__device__ int      g_lab_nz[BS];         // strict: any VALID gt w/ label!=0
__device__ int      g_mask_kind;
__device__ float    g_cls1, g_cls2, g_reg;  // zero-init; reset at end each run
__device__ unsigned g_bar_arrive, g_bar_gen;

__device__ __forceinline__ float fast_sqrtf(float x) {
    float r;
    asm("sqrt.approx.f32 %0, %1;" : "=f"(r) : "f"(x));
    return r;
}

// jax top_k total order: smaller cost wins; exact tie -> smaller query index.
__device__ __forceinline__ bool better(float va, int ia, float vb, int ib) {
    return (va < vb) || (va == vb && ia < ib);
}

__device__ __forceinline__ void grid_barrier() {
    __syncthreads();
    if (threadIdx.x == 0) {
        unsigned gen = atomicAdd(&g_bar_gen, 0u);   // read BEFORE arriving
        __threadfence();
        if (atomicAdd(&g_bar_arrive, 1u) == NBLOCKS - 1) {
            atomicExch(&g_bar_arrive, 0u);
            __threadfence();
            atomicAdd(&g_bar_gen, 1u);
        } else {
            while (atomicAdd(&g_bar_gen, 0u) == gen) __nanosleep(64);
        }
    }
    __syncthreads();
}

__device__ __forceinline__ float block_reduce_256(float v) {
    __shared__ float ws[8];
    __syncthreads();                        // protect ws across repeated calls
#pragma unroll
    for (int off = 16; off; off >>= 1) v += __shfl_xor_sync(0xffffffffu, v, off);
    if ((threadIdx.x & 31) == 0) ws[threadIdx.x >> 5] = v;
    __syncthreads();
    float t = 0.0f;
    if (threadIdx.x < 8) {
        t = ws[threadIdx.x];
#pragma unroll
        for (int off = 4; off; off >>= 1) t += __shfl_xor_sync(0xffu, t, off);
    }
    return t;   // valid in thread 0
}

// Identical code in phases A and C -> identical bins (required for scatter).
struct QP { float p0, p1, nll1, key; int bin; };
__device__ __forceinline__ QP qprob(const float* __restrict__ pl, int i, int lab) {
    float l0 = pl[2 * i], l1 = pl[2 * i + 1];
    float m  = fmaxf(l0, l1);
    float e0 = __expf(l0 - m), e1 = __expf(l1 - m);
    float sum = e0 + e1, inv = 1.0f / sum;
    QP r;
    r.p0 = e0 * inv; r.p1 = e1 * inv;
    r.nll1 = m + __logf(sum) - l1;
    r.key = lab ? fmaxf(r.p0, r.p1) : r.p0;   // lower bound on p_label
    r.bin = min(NBINS - 1, (int)(r.key * 256.0f));
    return r;
}

#define CEX3(va, ia, sa, vb, ib, sb)                                   \
    if (better(vb, ib, va, ia)) {                                      \
        float tv = va; va = vb; vb = tv;                               \
        int ti = ia; ia = ib; ib = ti;                                 \
        int ts = sa; sa = sb; sb = ts;                                 \
    }

#define INS(cst, qi, ps)                                                      \
    if (better(cst, qi, v3, i3)) {                                            \
        if (better(cst, qi, v1, i1)) {                                        \
            v3 = v2; i3 = i2; s3 = s2; v2 = v1; i2 = i1; s2 = s1;             \
            if (better(cst, qi, v0, i0)) {                                    \
                v1 = v0; i1 = i0; s1 = s0; v0 = cst; i0 = qi; s0 = ps;        \
            } else { v1 = cst; i1 = qi; s1 = ps; }                            \
        } else if (better(cst, qi, v2, i2)) {                                 \
            v3 = v2; i3 = i2; s3 = s2; v2 = cst; i2 = qi; s2 = ps;            \
        } else { v3 = cst; i3 = qi; s3 = ps; }                                \
    }

__global__ __launch_bounds__(NTHREADS, 1) void k_all(
    const float* __restrict__ pc, const float* __restrict__ pl,
    const float* __restrict__ gtc, const int* __restrict__ gtl,
    const unsigned char* __restrict__ gmsk, float* __restrict__ out)
{
    __shared__ union { unsigned u[NBINS]; float f[NCHUNK]; } sm;
    __shared__ int slab[BS];           // loose per-batch "any label != 0" flag
    const int tid  = threadIdx.x;
    const int gtid = blockIdx.x * NTHREADS + tid;
    const float PINF = __int_as_float(0x7f800000);
    const float NINF = __int_as_float(0xff800000);

    // Loose label flags (mask-independent; strict g_lab_nz implies these).
    if (tid < BS) slab[tid] = 0;
    __syncthreads();
    for (int j = tid; j < BS * NG; j += NTHREADS)
        if (gtl[j] != 0) slab[j >> 10] = 1;     // benign race: only writes 1
    __syncthreads();

    // ================= Phase A: compact (block 0) + softmax/hist (all) ======
    if (blockIdx.x == 0) {
        if (tid == 0) {
            bool any_mis = false, b1nz = false, any3f = false;
            for (int t = 0; t < 256; t++) {
                unsigned char v = gmsk[t];
                if ((t & 3) != 0 && v) {
                    any_mis = true;
                    if ((t & 3) == 1) b1nz = true;
                    if (v == 0x3F) any3f = true;
                }
            }
            g_mask_kind = !any_mis ? 0 : ((!b1nz && any3f) ? 2 : 1);
        }
        __syncthreads();
        int b = tid >> 5, lane = tid & 31, kind = g_mask_kind;
        int cnt = 0, labnz = 0;
        for (int j = 0; j < NG; j += 32) {
            int g = j + lane, i = b * NG + g;
            bool mk;
            if (kind == 0)      mk = ((const int*)gmsk)[i] != 0;
            else if (kind == 1) mk = gmsk[i] != 0;
            else                mk = ((const float*)gmsk)[i] != 0.0f;
            unsigned bal = __ballot_sync(0xffffffffu, mk);
            if (mk) {
                int pos = cnt + __popc(bal & ((1u << lane) - 1u));
                g_valid_list[b][pos] = g;
                if (gtl[i] != 0) labnz = 1;
            }
            cnt += __popc(bal);
        }
        unsigned lb = __ballot_sync(0xffffffffu, labnz);
        if (lane == 0) { g_valid_cnt[b] = cnt; g_lab_nz[b] = (lb != 0); }
    }
    float cls1 = 0.0f;
    for (int i = gtid; i < BS * NQ; i += GSZ) {
        int b = i >> 14;
        QP q = qprob(pl, i, slab[b]);
        atomicAdd(&g_hist[b * NBINS + q.bin], 1u);
        cls1 += q.nll1;
    }
    {
        float p = block_reduce_256(cls1);
        if (tid == 0) atomicAdd(&g_cls1, p);
    }
    grid_barrier();

    // ================= Phase B: descending-bin bases ========================
    if (blockIdx.x < BS) {
        int b = blockIdx.x;
        unsigned h0 = g_hist[b * NBINS + tid];
        sm.u[tid] = h0;
        __syncthreads();
        for (int off = 1; off < NBINS; off <<= 1) {
            unsigned v = (tid + off < NBINS) ? sm.u[tid + off] : 0u;
            __syncthreads();
            sm.u[tid] += v;
            __syncthreads();
        }
        g_cursor[b * NBINS + tid] = sm.u[tid] - h0;  // count of bins above
    }
    grid_barrier();

    // ================= Phase C: scatter + chunk min keys ====================
    for (int i = gtid; i < BS * NQ; i += GSZ) {
        int b = i >> 14, qi = i & (NQ - 1);
        QP q = qprob(pl, i, slab[b]);
        float x = pc[2 * i], y = pc[2 * i + 1];
        unsigned pos = atomicAdd(&g_cursor[b * NBINS + q.bin], 1u);
        g_sq[b * NQ + pos] = make_float4(x, y, -q.p0, __int_as_float(qi));
        // raw-uint max == float min (keys strictly negative)
        atomicMax(&g_chunkU[b * NCHUNK + (pos >> 5)], __float_as_uint(-q.key));
        if (g_lab_nz[b]) g_sp1[b * NQ + pos] = -q.p1;
    }
    grid_barrier();

    // ================= Phase D: split top-4 per gt ==========================
    // 64 blocks: block = (batch, 64-slot part). Lane = gt(8) x split(4).
    float v0 = PINF, v1 = PINF, v2 = PINF, v3 = NINF;
    int i0 = 0x7fffffff, i1 = 0x7fffffff, i2 = 0x7fffffff, i3 = 0x7fffffff;
    int s0 = 0, s1 = 0, s2 = 0, s3 = 0;
    bool leader = false;
    int bD = 0;
    float gx = 0.0f, gy = 0.0f;

    if (blockIdx.x < 64) {
        bD = blockIdx.x >> 3;
        int part = blockIdx.x & 7;
        int cnt = g_valid_cnt[bD];
        if (part * 64 < cnt) {                     // block-uniform
            sm.f[tid]       = __uint_as_float(g_chunkU[bD * NCHUNK + tid]);
            sm.f[tid + 256] = __uint_as_float(g_chunkU[bD * NCHUNK + tid + 256]);
            __syncthreads();
            for (int off = 1; off < NCHUNK; off <<= 1) {
                float a  = (tid + off < NCHUNK) ? sm.f[tid + off] : PINF;
                float b2 = (tid + 256 + off < NCHUNK) ? sm.f[tid + 256 + off] : PINF;
                __syncthreads();
                sm.f[tid]       = fminf(sm.f[tid], a);
                sm.f[tid + 256] = fminf(sm.f[tid + 256], b2);
                __syncthreads();
            }

            int w = tid >> 5, lane = tid & 31;
            int g = lane >> 2, s = lane & 3;
            int slot = part * 64 + w * 8 + g;
            bool act = slot < cnt;
            leader = act && (s == 0);
            int gi = g_valid_list[bD][act ? slot : 0];
            gx = gtc[(bD * NG + gi) * 2];
            gy = gtc[(bD * NG + gi) * 2 + 1];
            bool lab0 = (gtl[bD * NG + gi] == 0);
            if (act) v3 = PINF;                     // inactive: v3=-inf -> break

            const float4* __restrict__ qb = g_sq + bD * NQ;
            if (!g_lab_nz[bD]) {
                for (int c = s; c < NCHUNK; c += 4) {
                    if (sm.f[c] > v3) break;
                    int cb = c * 32;
#pragma unroll 4
                    for (int jj = 0; jj < 32; jj++) {
                        float4 q = qb[cb + jj];
                        float dx = q.x - gx, dy = q.y - gy;
                        float cst = fmaf(0.1f, fast_sqrtf(fmaf(dx, dx, dy * dy)), q.z);
                        if (cst <= v3) { int qi = __float_as_int(q.w); int ps = cb + jj; INS(cst, qi, ps); }
                    }
                }
            } else {
                const float* __restrict__ z1 = g_sp1 + bD * NQ;
                for (int c = s; c < NCHUNK; c += 4) {
                    if (sm.f[c] > v3) break;
                    int cb = c * 32;
                    for (int jj = 0; jj < 32; jj++) {
                        float4 q = qb[cb + jj];
                        float zc = lab0 ? q.z : z1[cb + jj];
                        float dx = q.x - gx, dy = q.y - gy;
                        float cst = fmaf(0.1f, fast_sqrtf(fmaf(dx, dx, dy * dy)), zc);
                        if (cst <= v3) { int qi = __float_as_int(q.w); int ps = cb + jj; INS(cst, qi, ps); }
                    }
                }
            }

            // Merge the 4 disjoint split lists per gt (xor 2, then 1).
#pragma unroll
            for (int off = 2; off >= 1; off >>= 1) {
                float w0 = __shfl_xor_sync(0xffffffffu, v0, off);
                float w1 = __shfl_xor_sync(0xffffffffu, v1, off);
                float w2 = __shfl_xor_sync(0xffffffffu, v2, off);
                float w3 = __shfl_xor_sync(0xffffffffu, v3, off);
                int j0 = __shfl_xor_sync(0xffffffffu, i0, off);
                int j1 = __shfl_xor_sync(0xffffffffu, i1, off);
                int j2 = __shfl_xor_sync(0xffffffffu, i2, off);
                int j3 = __shfl_xor_sync(0xffffffffu, i3, off);
                int t0 = __shfl_xor_sync(0xffffffffu, s0, off);
                int t1 = __shfl_xor_sync(0xffffffffu, s1, off);
                int t2 = __shfl_xor_sync(0xffffffffu, s2, off);
                int t3 = __shfl_xor_sync(0xffffffffu, s3, off);
                // lower half of bitonic merge-8
                if (better(w3, j3, v0, i0)) { v0 = w3; i0 = j3; s0 = t3; }
                if (better(w2, j2, v1, i1)) { v1 = w2; i1 = j2; s1 = t2; }
                if (better(w1, j1, v2, i2)) { v2 = w1; i2 = j1; s2 = t1; }
                if (better(w0, j0, v3, i3)) { v3 = w0; i3 = j0; s3 = t0; }
                // cleanup sort-4
                CEX3(v0, i0, s0, v2, i2, s2);
                CEX3(v1, i1, s1, v3, i3, s3);
                CEX3(v0, i0, s0, v1, i1, s1);
                CEX3(v2, i2, s2, v3, i3, s3);
            }
        }
    }

    // Epilogue: reg partial + match flags + cls correction (leaders only).
    float regs_ = 0.0f, corr = 0.0f;
    if (leader) {
        int ps4[4] = {s0, s1, s2, s3};
        int ii4[4] = {i0, i1, i2, i3};
        const float4* __restrict__ qb = g_sq + bD * NQ;
#pragma unroll
        for (int k = 0; k < 4; k++) {
            float4 q = qb[ps4[k]];
            float dx = q.x - gx, dy = q.y - gy;
            regs_ += dx * dx + dy * dy;
            int gidx = bD * NQ + ii4[k];
            if (atomicExch(&g_match[gidx], 1) == 0)   // first matcher pays corr
                corr += pl[2 * gidx + 1] - pl[2 * gidx];
        }
    }
    {
        float rsum = block_reduce_256(regs_);
        float csum = block_reduce_256(corr);
        if (tid == 0) {
            if (rsum != 0.0f) atomicAdd(&g_reg, rsum);
            if (csum != 0.0f) atomicAdd(&g_cls2, csum);
        }
    }
    grid_barrier();

    // ================= Phase E: output + cleanup for next replay ============
    if (leader) {                       // reset exactly the flags we set
        g_match[bD * NQ + i0] = 0;
        g_match[bD * NQ + i1] = 0;
        g_match[bD * NQ + i2] = 0;
        g_match[bD * NQ + i3] = 0;
    }
    if (blockIdx.x == 64)
        for (int j = tid; j < BS * NBINS; j += NTHREADS) g_hist[j] = 0u;
    if (blockIdx.x == 65)
        for (int j = tid; j < BS * NCHUNK; j += NTHREADS) g_chunkU[j] = 0u;
    if (blockIdx.x == 66 && tid == 0) {
        float R = atomicAdd(&g_reg, 0.0f);
        float A = atomicAdd(&g_cls1, 0.0f) + atomicAdd(&g_cls2, 0.0f);
        int n = 0;
#pragma unroll
        for (int b = 0; b < BS; b++) n += g_valid_cnt[b];
        float denom = 8.0f * (float)(n > 0 ? n : 1);   // n_valid*TOP_K*2
        out[0] = 5.0f * R / denom;
        out[1] = A / (float)(BS * NQ);
        g_reg = 0.0f; g_cls1 = 0.0f; g_cls2 = 0.0f;
    }
}

extern "C" void kernel_launch(void* const* d_in, const int* in_sizes, int n_in,
                              void* d_out, int out_size) {
    const float* pc   = (const float*)d_in[0];   // pred_coords (8,16384,2)
    const float* pl   = (const float*)d_in[1];   // pred_logits (8,16384,2)
    const float* gtc  = (const float*)d_in[2];   // gt_coords   (8,1024,2)
    const int*   gtl  = (const int*)d_in[3];     // gt_labels   (8,1024)
    const unsigned char* gmsk = (const unsigned char*)d_in[4];  // gt_masks

    k_all<<<NBLOCKS, NTHREADS>>>(pc, pl, gtc, gtl, gmsk, (float*)d_out);
}

// round 13
// speedup vs baseline: 1.9672x; 1.0339x over previous
#include <cuda_runtime.h>
#include <cstdint>

// DeNuCLoss: top-4 matching loss, single persistent kernel with software grid
// barriers. bs=8, nq=16384, ng=1024, N_CLS=1, TOP_K=4.
// cost = 0.1*dist(q,g) - p_label(q) >= -key (key = p0 if all labels 0, else
// max(p0,p1)). Queries bucket-sorted by descending key; each gt (split 4 ways
// across lanes) scans until suffix-min(-key) > its 4th-best cost.
// Phases: A softmax+smem-hist+compact | B bases | C 2-pass scatter | D top-4
// (ALL 128 blocks, 1024 slots/batch) | E output+cleanup.

#define BS 8
#define NQ 16384
#define NG 1024
#define NBINS 256
#define NCHUNK 512                 // NQ/32
#define NBLOCKS 128
#define NTHREADS 256

__device__ float4   g_sq[BS * NQ];        // sorted: x, y, -p0, idx(bits)
__device__ float    g_sp1[BS * NQ];       // sorted: -p1 (only if labels mixed)
__device__ int      g_match[BS * NQ];     // zero-init; reset in-kernel each run
__device__ unsigned g_hist[BS * NBINS];   // zero-init; reset at end each run
__device__ unsigned g_cursor[BS * NBINS];
__device__ unsigned g_chunkU[BS * NCHUNK];// zero-init; reset at end each run
__device__ int      g_valid_list[BS][NG];
__device__ int      g_valid_cnt[BS];
__device__ int      g_lab_nz[BS];         // strict: any VALID gt w/ label!=0
__device__ int      g_mask_kind;
__device__ float    g_cls1, g_cls2, g_reg;  // zero-init; reset at end each run
__device__ unsigned g_bar_arrive, g_bar_gen;

__device__ __forceinline__ float fast_sqrtf(float x) {
    float r;
    asm("sqrt.approx.f32 %0, %1;" : "=f"(r) : "f"(x));
    return r;
}

// jax top_k total order: smaller cost wins; exact tie -> smaller query index.
__device__ __forceinline__ bool better(float va, int ia, float vb, int ib) {
    return (va < vb) || (va == vb && ia < ib);
}

__device__ __forceinline__ void grid_barrier() {
    __syncthreads();
    if (threadIdx.x == 0) {
        unsigned gen = atomicAdd(&g_bar_gen, 0u);   // read BEFORE arriving
        __threadfence();
        if (atomicAdd(&g_bar_arrive, 1u) == NBLOCKS - 1) {
            atomicExch(&g_bar_arrive, 0u);
            __threadfence();
            atomicAdd(&g_bar_gen, 1u);
        } else {
            while (atomicAdd(&g_bar_gen, 0u) == gen) __nanosleep(64);
        }
    }
    __syncthreads();
}

__device__ __forceinline__ float block_reduce_256(float v) {
    __shared__ float ws[8];
    __syncthreads();                        // protect ws across repeated calls
#pragma unroll
    for (int off = 16; off; off >>= 1) v += __shfl_xor_sync(0xffffffffu, v, off);
    if ((threadIdx.x & 31) == 0) ws[threadIdx.x >> 5] = v;
    __syncthreads();
    float t = 0.0f;
    if (threadIdx.x < 8) {
        t = ws[threadIdx.x];
#pragma unroll
        for (int off = 4; off; off >>= 1) t += __shfl_xor_sync(0xffu, t, off);
    }
    return t;   // valid in thread 0
}

// Identical code in phases A and C -> identical bins (required for scatter).
struct QP { float p0, p1, nll1, key; int bin; };
__device__ __forceinline__ QP qprob(const float* __restrict__ pl, int i, int lab) {
    float l0 = pl[2 * i], l1 = pl[2 * i + 1];
    float m  = fmaxf(l0, l1);
    float e0 = __expf(l0 - m), e1 = __expf(l1 - m);
    float sum = e0 + e1, inv = 1.0f / sum;
    QP r;
    r.p0 = e0 * inv; r.p1 = e1 * inv;
    r.nll1 = m + __logf(sum) - l1;
    r.key = lab ? fmaxf(r.p0, r.p1) : r.p0;   // lower bound on p_label
    r.bin = min(NBINS - 1, (int)(r.key * 256.0f));
    return r;
}

#define CEX3(va, ia, sa, vb, ib, sb)                                   \
    if (better(vb, ib, va, ia)) {                                      \
        float tv = va; va = vb; vb = tv;                               \
        int ti = ia; ia = ib; ib = ti;                                 \
        int ts = sa; sa = sb; sb = ts;                                 \
    }

#define INS(cst, qi, ps)                                                      \
    if (better(cst, qi, v3, i3)) {                                            \
        if (better(cst, qi, v1, i1)) {                                        \
            v3 = v2; i3 = i2; s3 = s2; v2 = v1; i2 = i1; s2 = s1;             \
            if (better(cst, qi, v0, i0)) {                                    \
                v1 = v0; i1 = i0; s1 = s0; v0 = cst; i0 = qi; s0 = ps;        \
            } else { v1 = cst; i1 = qi; s1 = ps; }                            \
        } else if (better(cst, qi, v2, i2)) {                                 \
            v3 = v2; i3 = i2; s3 = s2; v2 = cst; i2 = qi; s2 = ps;            \
        } else { v3 = cst; i3 = qi; s3 = ps; }                                \
    }

__global__ __launch_bounds__(NTHREADS, 1) void k_all(
    const float* __restrict__ pc, const float* __restrict__ pl,
    const float* __restrict__ gtc, const int* __restrict__ gtl,
    const unsigned char* __restrict__ gmsk, float* __restrict__ out)
{
    __shared__ union { unsigned u[NBINS]; float f[NCHUNK]; } sm;
    __shared__ unsigned h2[NBINS];     // block scatter bases (phase C)
    __shared__ int slab[BS];           // loose per-batch "any label != 0" flag
    const int tid  = threadIdx.x;
    const int blkbase = blockIdx.x * 1024;     // block-contiguous item range
    const int bA = blkbase >> 14;              // this block's batch (16 blk/batch)
    const float PINF = __int_as_float(0x7f800000);
    const float NINF = __int_as_float(0xff800000);

    // Loose label flags (mask-independent; strict g_lab_nz implies these).
    if (tid < BS) slab[tid] = 0;
    __syncthreads();
    for (int j = tid; j < BS * NG; j += NTHREADS)
        if (gtl[j] != 0) slab[j >> 10] = 1;     // benign race: only writes 1
    __syncthreads();

    // ================= Phase A: compact (block 0) + softmax/smem-hist =======
    if (blockIdx.x == 0) {
        if (tid == 0) {
            bool any_mis = false, b1nz = false, any3f = false;
            for (int t = 0; t < 256; t++) {
                unsigned char v = gmsk[t];
                if ((t & 3) != 0 && v) {
                    any_mis = true;
                    if ((t & 3) == 1) b1nz = true;
                    if (v == 0x3F) any3f = true;
                }
            }
            g_mask_kind = !any_mis ? 0 : ((!b1nz && any3f) ? 2 : 1);
        }
        __syncthreads();
        int b = tid >> 5, lane = tid & 31, kind = g_mask_kind;
        int cnt = 0, labnz = 0;
        for (int j = 0; j < NG; j += 32) {
            int g = j + lane, i = b * NG + g;
            bool mk;
            if (kind == 0)      mk = ((const int*)gmsk)[i] != 0;
            else if (kind == 1) mk = gmsk[i] != 0;
            else                mk = ((const float*)gmsk)[i] != 0.0f;
            unsigned bal = __ballot_sync(0xffffffffu, mk);
            if (mk) {
                int pos = cnt + __popc(bal & ((1u << lane) - 1u));
                g_valid_list[b][pos] = g;
                if (gtl[i] != 0) labnz = 1;
            }
            cnt += __popc(bal);
        }
        unsigned lb = __ballot_sync(0xffffffffu, labnz);
        if (lane == 0) { g_valid_cnt[b] = cnt; g_lab_nz[b] = (lb != 0); }
    }
    sm.u[tid] = 0u;
    __syncthreads();
    float cls1 = 0.0f;
    {
        int labA = slab[bA];
#pragma unroll
        for (int k = 0; k < 4; k++) {
            int i = blkbase + tid + k * 256;
            QP q = qprob(pl, i, labA);
            atomicAdd(&sm.u[q.bin], 1u);      // smem histogram
            cls1 += q.nll1;
        }
    }
    __syncthreads();
    if (sm.u[tid]) atomicAdd(&g_hist[bA * NBINS + tid], sm.u[tid]);
    {
        float p = block_reduce_256(cls1);
        if (tid == 0) atomicAdd(&g_cls1, p);
    }
    grid_barrier();

    // ================= Phase B: descending-bin bases ========================
    if (blockIdx.x < BS) {
        int b = blockIdx.x;
        unsigned h0 = g_hist[b * NBINS + tid];
        sm.u[tid] = h0;
        __syncthreads();
        for (int off = 1; off < NBINS; off <<= 1) {
            unsigned v = (tid + off < NBINS) ? sm.u[tid + off] : 0u;
            __syncthreads();
            sm.u[tid] += v;
            __syncthreads();
        }
        g_cursor[b * NBINS + tid] = sm.u[tid] - h0;  // count of bins above
    }
    grid_barrier();

    // ================= Phase C: two-pass block scatter ======================
    {
        int labA = slab[bA];
        int labS = g_lab_nz[bA];
        QP qs[4]; float xs[4], ys[4];
        sm.u[tid] = 0u;
        __syncthreads();
#pragma unroll
        for (int k = 0; k < 4; k++) {
            int i = blkbase + tid + k * 256;
            qs[k] = qprob(pl, i, labA);
            xs[k] = pc[2 * i];
            ys[k] = pc[2 * i + 1];
            atomicAdd(&sm.u[qs[k].bin], 1u);
        }
        __syncthreads();
        unsigned cb_ = sm.u[tid];
        h2[tid] = cb_ ? atomicAdd(&g_cursor[bA * NBINS + tid], cb_) : 0u;
        __syncthreads();
        sm.u[tid] = 0u;
        __syncthreads();
#pragma unroll
        for (int k = 0; k < 4; k++) {
            int i = blkbase + tid + k * 256;
            int qi = i & (NQ - 1);
            unsigned r = atomicAdd(&sm.u[qs[k].bin], 1u);
            unsigned pos = h2[qs[k].bin] + r;
            g_sq[bA * NQ + pos] = make_float4(xs[k], ys[k], -qs[k].p0,
                                              __int_as_float(qi));
            // raw-uint max == float min (keys strictly negative)
            atomicMax(&g_chunkU[bA * NCHUNK + (pos >> 5)],
                      __float_as_uint(-qs[k].key));
            if (labS) g_sp1[bA * NQ + pos] = -qs[k].p1;
        }
    }
    grid_barrier();

    // ================= Phase D: split top-4 per gt ==========================
    // ALL 128 blocks: block = (batch[3b], part[4b]) -> 16 parts x 64 slots
    // = 1024 slots/batch (covers cnt up to NG). Lane = gt(8) x split(4).
    float v0 = PINF, v1 = PINF, v2 = PINF, v3 = NINF;
    int i0 = 0x7fffffff, i1 = 0x7fffffff, i2 = 0x7fffffff, i3 = 0x7fffffff;
    int s0 = 0, s1 = 0, s2 = 0, s3 = 0;
    bool leader = false;
    int bD = blockIdx.x >> 4;
    float gx = 0.0f, gy = 0.0f;

    {
        int part = blockIdx.x & 15;
        int cnt = g_valid_cnt[bD];
        if (part * 64 < cnt) {                     // block-uniform
            sm.f[tid]       = __uint_as_float(g_chunkU[bD * NCHUNK + tid]);
            sm.f[tid + 256] = __uint_as_float(g_chunkU[bD * NCHUNK + tid + 256]);
            __syncthreads();
            for (int off = 1; off < NCHUNK; off <<= 1) {
                float a  = (tid + off < NCHUNK) ? sm.f[tid + off] : PINF;
                float b2 = (tid + 256 + off < NCHUNK) ? sm.f[tid + 256 + off] : PINF;
                __syncthreads();
                sm.f[tid]       = fminf(sm.f[tid], a);
                sm.f[tid + 256] = fminf(sm.f[tid + 256], b2);
                __syncthreads();
            }

            int w = tid >> 5, lane = tid & 31;
            int g = lane >> 2, s = lane & 3;
            int slot = part * 64 + w * 8 + g;
            bool act = slot < cnt;
            leader = act && (s == 0);
            int gi = g_valid_list[bD][act ? slot : 0];
            gx = gtc[(bD * NG + gi) * 2];
            gy = gtc[(bD * NG + gi) * 2 + 1];
            bool lab0 = (gtl[bD * NG + gi] == 0);
            if (act) v3 = PINF;                     // inactive: v3=-inf -> break

            const float4* __restrict__ qb = g_sq + bD * NQ;
            if (!g_lab_nz[bD]) {
                for (int c = s; c < NCHUNK; c += 4) {
                    if (sm.f[c] > v3) break;
                    int cb = c * 32;
#pragma unroll 4
                    for (int jj = 0; jj < 32; jj++) {
                        float4 q = qb[cb + jj];
                        float dx = q.x - gx, dy = q.y - gy;
                        float cst = fmaf(0.1f, fast_sqrtf(fmaf(dx, dx, dy * dy)), q.z);
                        if (cst <= v3) { int qi = __float_as_int(q.w); int ps = cb + jj; INS(cst, qi, ps); }
                    }
                }
            } else {
                const float* __restrict__ z1 = g_sp1 + bD * NQ;
                for (int c = s; c < NCHUNK; c += 4) {
                    if (sm.f[c] > v3) break;
                    int cb = c * 32;
                    for (int jj = 0; jj < 32; jj++) {
                        float4 q = qb[cb + jj];
                        float zc = lab0 ? q.z : z1[cb + jj];
                        float dx = q.x - gx, dy = q.y - gy;
                        float cst = fmaf(0.1f, fast_sqrtf(fmaf(dx, dx, dy * dy)), zc);
                        if (cst <= v3) { int qi = __float_as_int(q.w); int ps = cb + jj; INS(cst, qi, ps); }
                    }
                }
            }

            // Merge the 4 disjoint split lists per gt (xor 2, then 1).
#pragma unroll
            for (int off = 2; off >= 1; off >>= 1) {
                float w0 = __shfl_xor_sync(0xffffffffu, v0, off);
                float w1 = __shfl_xor_sync(0xffffffffu, v1, off);
                float w2 = __shfl_xor_sync(0xffffffffu, v2, off);
                float w3 = __shfl_xor_sync(0xffffffffu, v3, off);
                int j0 = __shfl_xor_sync(0xffffffffu, i0, off);
                int j1 = __shfl_xor_sync(0xffffffffu, i1, off);
                int j2 = __shfl_xor_sync(0xffffffffu, i2, off);
                int j3 = __shfl_xor_sync(0xffffffffu, i3, off);
                int t0 = __shfl_xor_sync(0xffffffffu, s0, off);
                int t1 = __shfl_xor_sync(0xffffffffu, s1, off);
                int t2 = __shfl_xor_sync(0xffffffffu, s2, off);
                int t3 = __shfl_xor_sync(0xffffffffu, s3, off);
                // lower half of bitonic merge-8
                if (better(w3, j3, v0, i0)) { v0 = w3; i0 = j3; s0 = t3; }
                if (better(w2, j2, v1, i1)) { v1 = w2; i1 = j2; s1 = t2; }
                if (better(w1, j1, v2, i2)) { v2 = w1; i2 = j1; s2 = t1; }
                if (better(w0, j0, v3, i3)) { v3 = w0; i3 = j0; s3 = t0; }
                // cleanup sort-4
                CEX3(v0, i0, s0, v2, i2, s2);
                CEX3(v1, i1, s1, v3, i3, s3);
                CEX3(v0, i0, s0, v1, i1, s1);
                CEX3(v2, i2, s2, v3, i3, s3);
            }
        }
    }

    // Epilogue: reg partial + match flags + cls correction (leaders only).
    float regs_ = 0.0f, corr = 0.0f;
    if (leader) {
        int ps4[4] = {s0, s1, s2, s3};
        int ii4[4] = {i0, i1, i2, i3};
        const float4* __restrict__ qb = g_sq + bD * NQ;
#pragma unroll
        for (int k = 0; k < 4; k++) {
            float4 q = qb[ps4[k]];
            float dx = q.x - gx, dy = q.y - gy;
            regs_ += dx * dx + dy * dy;
            int gidx = bD * NQ + ii4[k];
            if (atomicExch(&g_match[gidx], 1) == 0)   // first matcher pays corr
                corr += pl[2 * gidx + 1] - pl[2 * gidx];
        }
    }
    {
        float rsum = block_reduce_256(regs_);
        float csum = block_reduce_256(corr);
        if (tid == 0) {
            if (rsum != 0.0f) atomicAdd(&g_reg, rsum);
            if (csum != 0.0f) atomicAdd(&g_cls2, csum);
        }
    }
    grid_barrier();

    // ================= Phase E: output + cleanup for next replay ============
    if (leader) {                       // reset exactly the flags we set
        g_match[bD * NQ + i0] = 0;
        g_match[bD * NQ + i1] = 0;
        g_match[bD * NQ + i2] = 0;
        g_match[bD * NQ + i3] = 0;
    }
    if (blockIdx.x == 64)
        for (int j = tid; j < BS * NBINS; j += NTHREADS) g_hist[j] = 0u;
    if (blockIdx.x == 65)
        for (int j = tid; j < BS * NCHUNK; j += NTHREADS) g_chunkU[j] = 0u;
    if (blockIdx.x == 66 && tid == 0) {
        float R = atomicAdd(&g_reg, 0.0f);
        float A = atomicAdd(&g_cls1, 0.0f) + atomicAdd(&g_cls2, 0.0f);
        int n = 0;
#pragma unroll
        for (int b = 0; b < BS; b++) n += g_valid_cnt[b];
        float denom = 8.0f * (float)(n > 0 ? n : 1);   // n_valid*TOP_K*2
        out[0] = 5.0f * R / denom;
        out[1] = A / (float)(BS * NQ);
        g_reg = 0.0f; g_cls1 = 0.0f; g_cls2 = 0.0f;
    }
}

extern "C" void kernel_launch(void* const* d_in, const int* in_sizes, int n_in,
                              void* d_out, int out_size) {
    const float* pc   = (const float*)d_in[0];   // pred_coords (8,16384,2)
    const float* pl   = (const float*)d_in[1];   // pred_logits (8,16384,2)
    const float* gtc  = (const float*)d_in[2];   // gt_coords   (8,1024,2)
    const int*   gtl  = (const int*)d_in[3];     // gt_labels   (8,1024)
    const unsigned char* gmsk = (const unsigned char*)d_in[4];  // gt_masks

    k_all<<<NBLOCKS, NTHREADS>>>(pc, pl, gtc, gtl, gmsk, (float*)d_out);
}